// round 17
// baseline (speedup 1.0000x reference)
#include <cuda_runtime.h>
#include <math.h>

#define EMAX 4096
#define NB2  256
#define W    8
#define CAPW (EMAX*EMAX/2 + EMAX)     /* one-sided window-slot buffer */
#define CAPC 65536                    /* candidate cap per rank */
#define PI_F   3.14159274101257324f
#define THR_F  0.08726646259971647f
#define BSCALE 81.48733086305042f     /* 256/pi */
#define INF_BITS 0x7F800000u
#define GRID 256
#define NTHR 512

// ---- device scratch (no allocations allowed) ----
__device__ float4   g_i4[EMAX];
__device__ float2   g_mid[EMAX];
__device__ int      g_bine[EMAX];
__device__ unsigned g_bcnt[NB2], g_bcur[NB2];
__device__ unsigned g_boff[NB2 + 1];
__device__ unsigned g_Bb[NB2 + 1];
__device__ float4   g_q4[EMAX];
__device__ float4   g_l4[EMAX];
__device__ __align__(16) float g_bufw[CAPW];
__device__ unsigned g_hA[2048];        // float bits [21..31]
__device__ float    g_cand[3 * CAPC];  // candidate values per rank
__device__ unsigned g_candn[3];
__device__ unsigned g_done;
__device__ double   g_sum;
// monotone grid-barrier state (never reset; replay-safe)
__device__ unsigned g_arrive_v;
__device__ unsigned g_sense_v;

// ---------------------------------------------------------------------------
__device__ __forceinline__ void gsync(unsigned base, unsigned& bidx)
{
    __syncthreads();
    if (threadIdx.x == 0) {
        unsigned target = base + (++bidx);
        __threadfence();
        unsigned old = atomicAdd(&g_arrive_v, 1u);
        if (old + 1u == target * GRID) {
            __threadfence();
            *(volatile unsigned*)&g_sense_v = target;
        } else {
            while ((int)(*(volatile unsigned*)&g_sense_v - target) < 0)
                __nanosleep(64);
        }
        __threadfence();
    }
    __syncthreads();
}

// Shuffle-based inclusive block scan over 512 threads (3 barriers).
__device__ __forceinline__ unsigned bscan(unsigned v, unsigned* ws, unsigned* total)
{
    int lane = threadIdx.x & 31, w = threadIdx.x >> 5;
    #pragma unroll
    for (int o = 1; o < 32; o <<= 1) {
        unsigned x = __shfl_up_sync(0xFFFFFFFFu, v, o);
        if (lane >= o) v += x;
    }
    if (lane == 31) ws[w] = v;
    __syncthreads();
    if (w == 0) {
        unsigned s = (lane < 16) ? ws[lane] : 0u;
        #pragma unroll
        for (int o = 1; o < 16; o <<= 1) {
            unsigned x = __shfl_up_sync(0xFFFFFFFFu, s, o);
            if (lane >= o) s += x;
        }
        if (lane < 16) ws[lane] = s;
    }
    __syncthreads();
    unsigned basep = (w > 0) ? ws[w - 1] : 0u;
    unsigned tot   = ws[15];
    __syncthreads();
    *total = tot;
    return v + basep;
}

// ---------------------------------------------------------------------------
// K1: zero scratch + per-edge geometry + bucket counts.  <<<32,256>>>
// ---------------------------------------------------------------------------
__global__ void k_setup(const float* __restrict__ pos, const int* __restrict__ eidx, int E)
{
    int gtid = blockIdx.x * blockDim.x + threadIdx.x;
    int nt   = gridDim.x * blockDim.x;
    for (int k = gtid; k < 2048; k += nt) g_hA[k] = 0u;
    if (gtid < NB2) { g_bcnt[gtid] = 0u; g_bcur[gtid] = 0u; }
    if (gtid < 3)   g_candn[gtid] = 0u;
    if (gtid == 0)  { g_sum = 0.0; g_done = 0u; }

    if (gtid < E) {
        int e = gtid;
        int s = eidx[e];
        int d = eidx[E + e];
        float sx = pos[2*s], sy = pos[2*s+1];
        float dx = pos[2*d], dy = pos[2*d+1];
        float vx = dx - sx, vy = dy - sy;
        float len = fmaxf(sqrtf(vx*vx + vy*vy), 1e-8f);
        float ux = vx / len, uy = vy / len;
        float a = atan2f(uy, ux);
        a = fmodf(a, PI_F);
        if (a < 0.f) a += PI_F;
        float nx = -uy, ny = ux;
        g_i4[e]  = make_float4(a, nx, ny, sx*nx + sy*ny);
        g_mid[e] = make_float2((sx + dx) * 0.5f, (sy + dy) * 0.5f);
        int b = (int)(a * BSCALE);
        if (b >= NB2) b = NB2 - 1;
        if (b < 0)    b = 0;
        g_bine[e] = b;
        atomicAdd(&g_bcnt[b], 1u);
    }
}

// ---------------------------------------------------------------------------
// K2: redundant per-block scans + bucket scatter.  <<<16,256>>>
// ---------------------------------------------------------------------------
__global__ void k_fill(int E)
{
    __shared__ unsigned sOff[NB2 + 1];
    __shared__ unsigned ssc[NB2];
    int t = threadIdx.x;

    unsigned c = g_bcnt[t];
    ssc[t] = c;
    __syncthreads();
    #pragma unroll
    for (int off = 1; off < NB2; off <<= 1) {
        unsigned v = ssc[t];
        unsigned a = (t >= off) ? ssc[t - off] : 0u;
        __syncthreads();
        ssc[t] = v + a;
        __syncthreads();
    }
    unsigned exc = ssc[t] - c;
    sOff[t] = exc;
    g_boff[t] = exc;
    if (t == NB2 - 1) { sOff[NB2] = ssc[NB2 - 1]; g_boff[NB2] = ssc[NB2 - 1]; }
    __syncthreads();

    {
        int b = t;
        unsigned o = sOff[b];
        unsigned U = sOff[(b + 9 <= NB2) ? (b + 9) : NB2];
        unsigned X = (b <= 7) ? (sOff[NB2] - sOff[b + 248]) : 0u;
        unsigned S = c * (U - 1u + X) - c * o - (c * (c - 1u)) / 2u;
        ssc[t] = S;
        __syncthreads();
        #pragma unroll
        for (int off = 1; off < NB2; off <<= 1) {
            unsigned v = ssc[t];
            unsigned a = (t >= off) ? ssc[t - off] : 0u;
            __syncthreads();
            ssc[t] = v + a;
            __syncthreads();
        }
        g_Bb[t] = ssc[t] - S;
        if (t == NB2 - 1) g_Bb[NB2] = ssc[NB2 - 1];
    }
    __syncthreads();

    int e = blockIdx.x * blockDim.x + t;
    if (e < E) {
        int b = g_bine[e];
        unsigned slot = sOff[b] + atomicAdd(&g_bcur[b], 1u);
        float4 f = g_i4[e];
        float2 m = g_mid[e];
        g_q4[slot] = make_float4(f.x, m.x, m.y, __int_as_float(e));
        g_l4[slot] = make_float4(f.y, f.z, f.w, 0.f);
    }
}

// ---------------------------------------------------------------------------
// K3: ONE-SIDED enumeration (unchanged from R12/R13).  <<<256,512>>>
// ---------------------------------------------------------------------------
__global__ void __launch_bounds__(512) k_enum(int E)
{
    __shared__ unsigned sb[NB2 + 1];
    __shared__ unsigned sB[NB2];
    __shared__ unsigned sh[2048];
    int t = threadIdx.x;
    for (int k = t; k <= NB2; k += 512) sb[k] = g_boff[k];
    for (int k = t; k < NB2;  k += 512) sB[k] = g_Bb[k];
    for (int k = t; k < 2048; k += 512) sh[k] = 0u;
    __syncthreads();

    int gw   = (blockIdx.x * blockDim.x + t) >> 5;
    int lane = t & 31;
    int nw   = (gridDim.x * blockDim.x) >> 5;

    for (int s = gw; s < E; s += nw) {
        float4 qs = g_q4[s];
        int u = __float_as_int(qs.w);
        float au = qs.x, mxu = qs.y, myu = qs.z;
        float4 lu = g_l4[s];
        float nxu = lu.x, nyu = lu.y, cu = lu.z;
        int b = g_bine[u];

        int o = (int)sb[b];
        int U = (int)sb[(b + 9 <= NB2) ? (b + 9) : NB2];
        int X = (b <= 7) ? (int)(sb[NB2] - sb[b + 248]) : 0;

        int so = s - o;
        unsigned obase = sB[b] + (unsigned)(so * (U - 1 + X)) - (unsigned)(((o + s - 1) * so) / 2);
        int cnt_f = U - s - 1;

        for (int k = s + 1 + lane; k < U; k += 32) {
            float4 q = g_q4[k];
            float da   = fabsf(au - q.x);
            float circ = fminf(da, PI_F - da);
            float val  = __uint_as_float(INF_BITS);
            if (circ <= THR_F) {                     // exact reference mask
                int ov = __float_as_int(q.w);
                if (u < ov) {
                    val = fabsf(fmaf(nxu, q.y, fmaf(nyu, q.z, -cu)));
                } else {
                    float4 lv = g_l4[k];
                    val = fabsf(fmaf(lv.x, mxu, fmaf(lv.y, myu, -lv.z)));
                }
                atomicAdd(&sh[__float_as_uint(val) >> 21], 1u);
            }
            g_bufw[obase + (unsigned)(k - s - 1)] = val;
        }
        if (X > 0) {
            int wsrt = (int)sb[b + 248];
            int wend = (int)sb[NB2];
            for (int k = wsrt + lane; k < wend; k += 32) {
                float4 q = g_q4[k];
                float da   = fabsf(au - q.x);
                float circ = fminf(da, PI_F - da);
                float val  = __uint_as_float(INF_BITS);
                if (circ <= THR_F) {
                    int ov = __float_as_int(q.w);
                    if (u < ov) {
                        val = fabsf(fmaf(nxu, q.y, fmaf(nyu, q.z, -cu)));
                    } else {
                        float4 lv = g_l4[k];
                        val = fabsf(fmaf(lv.x, mxu, fmaf(lv.y, myu, -lv.z)));
                    }
                    atomicAdd(&sh[__float_as_uint(val) >> 21], 1u);
                }
                g_bufw[obase + (unsigned)(cnt_f + (k - wsrt))] = val;
            }
        }
    }
    __syncthreads();
    for (int k = t; k < 2048; k += 512) {
        unsigned v = sh[k];
        if (v) atomicAdd(&g_hA[k], v);
    }
}

// ---------------------------------------------------------------------------
// K4 (FUSED SELECT): pickA (no buffer read) + WARP-UNIFORM candidate
//     collection stream | gsync | redundant shared-mem exact pick + loss
//     stream + finalize.  <<<GRID,512>>>
// ---------------------------------------------------------------------------
__global__ void __launch_bounds__(512) k_select_loss(float* __restrict__ out)
{
    __shared__ unsigned ws[16];
    __shared__ unsigned sbin[256];
    __shared__ unsigned sp[3], srA[3];
    __shared__ unsigned spick[2];
    __shared__ float    sq[3];
    __shared__ unsigned s_sense;
    int t = threadIdx.x;
    if (t == 0) s_sense = *(volatile unsigned*)&g_sense_v;
    if (t < 3) { sp[t] = 0xFFFFFFFFu; srA[t] = 0u; sq[t] = 0.f; }
    __syncthreads();
    const unsigned sbase = s_sense;
    unsigned bidx = 0;

    const unsigned T  = g_Bb[NB2];
    const unsigned T4 = (T + 3u) >> 2;               // include partial final vec
    const float4* buf4 = (const float4*)g_bufw;
    const unsigned stride = GRID * NTHR;
    const unsigned gt = blockIdx.x * NTHR + t;
    const int lane = t & 31;

    // ---------------- phase 1: pickA (histogram only) + collect ----------
    unsigned n;
    {
        unsigned loc[4], s = 0;
        #pragma unroll
        for (int k = 0; k < 4; k++) { loc[k] = g_hA[t*4 + k]; s += loc[k]; }
        unsigned inc = bscan(s, ws, &n);
        unsigned exc = inc - s;

        if (n) {
            unsigned r[3];
            r[0] = (n/4 > 0u) ? (n/4 - 1u) : 0u;
            r[1] = n/2;
            unsigned q3i = (unsigned)((3ull * n) / 4ull);
            if (q3i > n - 1u) q3i = n - 1u;
            r[2] = q3i;
            #pragma unroll
            for (int st = 0; st < 3; st++) {
                if (s && exc <= r[st] && r[st] < inc) {
                    unsigned cum = exc;
                    #pragma unroll
                    for (int k = 0; k < 4; k++) {
                        if (cum + loc[k] > r[st]) {
                            sp[st]  = (unsigned)(t*4 + k);
                            srA[st] = r[st] - cum;
                            break;
                        }
                        cum += loc[k];
                    }
                }
            }
        }
        __syncthreads();

        if (n) {
            // WARP-UNIFORM collect: chunk base is warp-uniform, lane offset
            // inside; every lane executes every sync op every iteration.
            unsigned p0 = sp[0], p1 = sp[1], p2 = sp[2];
            unsigned gwarp = gt >> 5;
            unsigned nwarp = stride >> 5;
            for (unsigned c4 = gwarp * 32u; c4 < T4; c4 += nwarp * 32u) {
                unsigned i4 = c4 + (unsigned)lane;
                bool valid = (i4 < T4);
                float4 v4;
                if (valid) v4 = buf4[i4];
                else       v4 = make_float4(__uint_as_float(INF_BITS), __uint_as_float(INF_BITS),
                                            __uint_as_float(INF_BITS), __uint_as_float(INF_BITS));
                // mask out elements past T in the final partial vector
                unsigned eBase = i4 << 2;
                bool m0a=false,m1a=false,m2a=false,m0b=false,m1b=false,m2b=false,
                     m0c=false,m1c=false,m2c=false,m0d=false,m1d=false,m2d=false;
                if (valid) {
                    unsigned pa;
                    if (eBase + 0 < T) { pa = __float_as_uint(v4.x) >> 21; m0a=(pa==p0); m1a=(pa==p1); m2a=(pa==p2); }
                    if (eBase + 1 < T) { pa = __float_as_uint(v4.y) >> 21; m0b=(pa==p0); m1b=(pa==p1); m2b=(pa==p2); }
                    if (eBase + 2 < T) { pa = __float_as_uint(v4.z) >> 21; m0c=(pa==p0); m1c=(pa==p1); m2c=(pa==p2); }
                    if (eBase + 3 < T) { pa = __float_as_uint(v4.w) >> 21; m0d=(pa==p0); m1d=(pa==p1); m2d=(pa==p2); }
                }
                bool any = m0a|m1a|m2a|m0b|m1b|m2b|m0c|m1c|m2c|m0d|m1d|m2d;
                if (__any_sync(0xFFFFFFFFu, any)) {
                    #pragma unroll
                    for (int c = 0; c < 4; c++) {
                        float vf = (c == 0 ? v4.x : c == 1 ? v4.y : c == 2 ? v4.z : v4.w);
                        bool m0 = (c==0?m0a:c==1?m0b:c==2?m0c:m0d);
                        bool m1 = (c==0?m1a:c==1?m1b:c==2?m1c:m1d);
                        bool m2 = (c==0?m2a:c==1?m2b:c==2?m2c:m2d);
                        #pragma unroll
                        for (int st = 0; st < 3; st++) {
                            bool m = (st == 0 ? m0 : st == 1 ? m1 : m2);
                            unsigned ball = __ballot_sync(0xFFFFFFFFu, m);
                            if (ball) {
                                int leader = __ffs(ball) - 1;
                                unsigned bb = 0;
                                if (lane == leader) bb = atomicAdd(&g_candn[st], (unsigned)__popc(ball));
                                bb = __shfl_sync(0xFFFFFFFFu, bb, leader);
                                if (m) {
                                    unsigned p = bb + __popc(ball & ((1u << lane) - 1u));
                                    if (p < CAPC) g_cand[st * CAPC + p] = vf;
                                }
                            }
                        }
                    }
                }
            }
        }
    }
    gsync(sbase, bidx);                                    // B1

    // ---------------- phase 2: redundant exact pick + loss ----------------
    double acc = 0.0;
    if (n) {
        for (int st = 0; st < 3; st++) {
            unsigned cnt = g_candn[st]; if (cnt > CAPC) cnt = CAPC;
            unsigned r   = srA[st];
            const float* cd = &g_cand[st * CAPC];

            // round 1: bits [13:21)
            if (t < 256) sbin[t] = 0u;
            __syncthreads();
            for (unsigned i = t; i < cnt; i += NTHR)
                atomicAdd(&sbin[(__float_as_uint(cd[i]) >> 13) & 255u], 1u);
            __syncthreads();
            unsigned h = (t < 256) ? sbin[t] : 0u, tot;
            unsigned inc = bscan(h, ws, &tot);
            unsigned exc = inc - h;
            if (t < 256 && h && exc <= r && r < inc) { spick[0] = (unsigned)t; spick[1] = r - exc; }
            __syncthreads();
            unsigned b1 = spick[0], r2 = spick[1];
            __syncthreads();

            // round 2: bits [5:13), filtered by b1
            if (t < 256) sbin[t] = 0u;
            __syncthreads();
            for (unsigned i = t; i < cnt; i += NTHR) {
                unsigned bits = __float_as_uint(cd[i]);
                if (((bits >> 13) & 255u) == b1) atomicAdd(&sbin[(bits >> 5) & 255u], 1u);
            }
            __syncthreads();
            h = (t < 256) ? sbin[t] : 0u;
            inc = bscan(h, ws, &tot);
            exc = inc - h;
            if (t < 256 && h && exc <= r2 && r2 < inc) { spick[0] = (unsigned)t; spick[1] = r2 - exc; }
            __syncthreads();
            unsigned b2 = spick[0], r3 = spick[1];
            __syncthreads();

            // round 3: bits [0:5), filtered by b1,b2 (32 bins)
            if (t < 256) sbin[t] = 0u;
            __syncthreads();
            for (unsigned i = t; i < cnt; i += NTHR) {
                unsigned bits = __float_as_uint(cd[i]);
                if (((bits >> 13) & 255u) == b1 && ((bits >> 5) & 255u) == b2)
                    atomicAdd(&sbin[bits & 31u], 1u);
            }
            __syncthreads();
            h = (t < 32) ? sbin[t] : 0u;
            inc = bscan(h, ws, &tot);
            exc = inc - h;
            if (t < 32 && h && exc <= r3 && r3 < inc)
                sq[st] = __uint_as_float((sp[st] << 21) | (b1 << 13) | (b2 << 5) | (unsigned)t);
            __syncthreads();
        }

        float mu = sq[1];
        float margin = fmaxf(sq[2] - sq[0], 1e-6f) * 0.75f;   // iqr * 0.5 * 1.5

        // loss stream (no warp syncs — per-lane loop is fine)
        unsigned Tv = T >> 2;
        for (unsigned i4 = gt; i4 < Tv; i4 += stride) {
            float4 v4 = buf4[i4];
            #pragma unroll
            for (int c = 0; c < 4; c++) {
                float d = (c == 0 ? v4.x : c == 1 ? v4.y : c == 2 ? v4.z : v4.w);
                if (__float_as_uint(d) < INF_BITS) {
                    float h2 = fabsf(d - mu) - margin;
                    if (h2 > 0.f) acc += (double)h2;
                }
            }
        }
        for (unsigned idx = (Tv << 2) + gt; idx < T; idx += stride) {
            float d = g_bufw[idx];
            if (__float_as_uint(d) < INF_BITS) {
                float h2 = fabsf(d - mu) - margin;
                if (h2 > 0.f) acc += (double)h2;
            }
        }
    }

    for (int o = 16; o; o >>= 1) acc += __shfl_down_sync(0xFFFFFFFFu, acc, o);
    __shared__ double shs[16];
    if ((t & 31) == 0) shs[t >> 5] = acc;
    __syncthreads();
    if (t < 32) {
        double v = (t < 16) ? shs[t] : 0.0;
        for (int o = 8; o; o >>= 1) v += __shfl_down_sync(0xFFFFFFFFu, v, o);
        if (t == 0 && v != 0.0) atomicAdd(&g_sum, v);
    }
    __shared__ bool last;
    if (t == 0) {
        __threadfence();
        last = (atomicAdd(&g_done, 1u) == gridDim.x - 1);
    }
    __syncthreads();
    if (last && t == 0) {
        __threadfence();
        double denom = (double)(n > 0u ? n : 1u);
        out[0] = (float)(*(volatile double*)&g_sum / denom);
    }
}

// ---------------------------------------------------------------------------
extern "C" void kernel_launch(void* const* d_in, const int* in_sizes, int n_in,
                              void* d_out, int out_size)
{
    const float* pos  = (const float*)d_in[0];   // node_positions (B*N, 2)
    // d_in[1] = adjacency: unused
    const int*   eidx = (const int*)d_in[2];     // edge_index (2, E)
    float* out = (float*)d_out;

    int E = in_sizes[2] / 2;
    if (E > EMAX) E = EMAX;

    k_setup<<<32, 256>>>(pos, eidx, E);
    k_fill<<<16, 256>>>(E);
    k_enum<<<256, 512>>>(E);
    k_select_loss<<<GRID, NTHR>>>(out);
}